// round 16
// baseline (speedup 1.0000x reference)
#include <cuda_runtime.h>
#include <cuda_bf16.h>
#include <cuda_fp16.h>
#include <stdint.h>

#define DI __device__ __forceinline__

// ---------------- scratch (static device globals; no allocation) ----------------
#define SCR_ELEMS (4u * 8u * 2048u * 64u)  // 4,194,304
__device__ __align__(16) __half g_qh[SCR_ELEMS];      // Q fp16: [B,H,S,D]
__device__ __align__(16) __half g_kh[SCR_ELEMS];      // K fp16: [B,H,S,D]
__device__ __align__(16) __half g_vh[SCR_ELEMS];      // V^T fp16: [B,H,D,S]
__device__ __align__(16) __half g_oh[SCR_ELEMS];      // AO fp16: [8192, 512]
__device__ __align__(16) __half g_xh[SCR_ELEMS];      // x fp16: [8192, 512]
__device__ __align__(16) __half g_wh[4u * 262144u];   // Wq,Wk,Wv,Wo fp16

// ---------------- helpers ----------------
DI uint32_t smem_u32(const void* p) {
    uint32_t a;
    asm("{ .reg .u64 t; cvta.to.shared.u64 t, %1; cvt.u32.u64 %0, t; }" : "=r"(a) : "l"(p));
    return a;
}
DI void ldsm4(uint32_t* r, uint32_t a) {
    asm volatile("ldmatrix.sync.aligned.m8n8.x4.shared.b16 {%0,%1,%2,%3}, [%4];"
                 : "=r"(r[0]), "=r"(r[1]), "=r"(r[2]), "=r"(r[3]) : "r"(a));
}
DI void mma_f16(float* c, const uint32_t* a, const uint32_t* b) {
    asm volatile(
        "mma.sync.aligned.m16n8k16.row.col.f32.f16.f16.f32 "
        "{%0,%1,%2,%3}, {%4,%5,%6,%7}, {%8,%9}, {%0,%1,%2,%3};"
        : "+f"(c[0]), "+f"(c[1]), "+f"(c[2]), "+f"(c[3])
        : "r"(a[0]), "r"(a[1]), "r"(a[2]), "r"(a[3]), "r"(b[0]), "r"(b[1]));
}
DI void cp16(uint32_t dst, const void* src) {
    asm volatile("cp.async.cg.shared.global [%0], [%1], 16;" :: "r"(dst), "l"(src));
}
DI void cp_commit() { asm volatile("cp.async.commit_group;" ::: "memory"); }
template <int N> DI void cp_wait() { asm volatile("cp.async.wait_group %0;" :: "n"(N) : "memory"); }

DI uint32_t packh2(float a, float b) {
    __half2 h = __floats2half2_rn(a, b);
    return *reinterpret_cast<uint32_t*>(&h);
}
// sigmoid(qk/8 - log 2048) = 0.5 + 0.5*tanh((qk/8 - log2048)/2)  — fp32 MUFU
DI float sigmoid_tanh(float qk) {
    float t = fmaf(qk, 0.0625f, -3.81230949f);  // qk/16 - log(2048)/2
    float th;
    asm("tanh.approx.f32 %0, %1;" : "=f"(th) : "f"(t));
    return fmaf(th, 0.5f, 0.5f);
}

// =====================================================================
// Kernel 0: pre-convert x and weights to fp16.
// =====================================================================
__global__ __launch_bounds__(256) void k_split(const float* __restrict__ x,
                                               const float* __restrict__ Wq,
                                               const float* __restrict__ Wk,
                                               const float* __restrict__ Wv,
                                               const float* __restrict__ Wo) {
    size_t idx = (size_t)blockIdx.x * 256 + threadIdx.x;
    if (idx < 1048576) {
        float4 f = ((const float4*)x)[idx];
        ((uint2*)g_xh)[idx] = make_uint2(packh2(f.x, f.y), packh2(f.z, f.w));
    } else {
        size_t r = idx - 1048576;
        int ws = (int)(r >> 16);
        size_t off = r & 65535;
        const float* src = (ws == 0) ? Wq : (ws == 1) ? Wk : (ws == 2) ? Wv : Wo;
        float4 f = ((const float4*)src)[off];
        ((uint2*)(g_wh + (size_t)ws * 262144))[off] =
            make_uint2(packh2(f.x, f.y), packh2(f.z, f.w));
    }
}

// =====================================================================
// Shared proj-GEMM: BM=128 BN=64 BK=64, 256 thr (8 warps 4m x 2n),
// 3-stage cp.async ring (wait<1>), single-combo A_fp16 @ B_fp16.
// stage elems: 13824.  layout: A [0,9216) B [9216,13824)
// =====================================================================
constexpr int RST = 72;   // padded row stride (elems) for 64-col tiles
constexpr int PST = 13824;
constexpr int PROJ_SMEM = 3 * PST * 2;  // 82944 B

template <typename EPI>
DI void proj_gemm(const __half* __restrict__ A, const __half* __restrict__ B,
                  int m0, int n0, EPI epi) {
    extern __shared__ __half dsm[];
    const uint32_t u0 = smem_u32(dsm);
    const int tid = threadIdx.x, lid = tid & 31, w = tid >> 5;
    const int wm = w >> 1, wn = w & 1;

    auto load_stage = [&](int c, int s) {
        uint32_t base = u0 + (uint32_t)(s * PST * 2);
        const int r0 = tid >> 3, q = tid & 7;
#pragma unroll
        for (int it = 0; it < 4; it++) {
            int r = r0 + it * 32;
            size_t src = (size_t)(m0 + r) * 512 + c * 64 + q * 8;
            cp16(base + (uint32_t)((r * RST + q * 8) * 2), A + src);
        }
#pragma unroll
        for (int it = 0; it < 2; it++) {
            int r = r0 + it * 32;
            size_t src = (size_t)(n0 + r) * 512 + c * 64 + q * 8;
            cp16(base + 18432u + (uint32_t)((r * RST + q * 8) * 2), B + src);
        }
    };

    float acc[2][4][4];
#pragma unroll
    for (int mf = 0; mf < 2; mf++)
#pragma unroll
        for (int nf = 0; nf < 4; nf++)
#pragma unroll
            for (int e = 0; e < 4; e++) acc[mf][nf][e] = 0.0f;

    load_stage(0, 0); cp_commit();
    load_stage(1, 1); cp_commit();

    for (int c = 0; c < 8; c++) {
        if (c < 7) cp_wait<1>(); else cp_wait<0>();
        __syncthreads();
        if (c < 6) { load_stage(c + 2, (c + 2) % 3); cp_commit(); }

        const uint32_t bA = u0 + (uint32_t)((c % 3) * PST * 2);
        const uint32_t uA = bA, uB = bA + 18432u;

#pragma unroll
        for (int kh = 0; kh < 2; kh++) {
            uint32_t af[2][2][4];
#pragma unroll
            for (int mf = 0; mf < 2; mf++)
#pragma unroll
                for (int kk = 0; kk < 2; kk++) {
                    uint32_t off = (uint32_t)(((wm * 32 + mf * 16 + (lid & 15)) * RST +
                                               kh * 32 + kk * 16 + (lid >> 4) * 8) * 2);
                    ldsm4(af[mf][kk], uA + off);
                }
#pragma unroll
            for (int nf = 0; nf < 4; nf++) {
                uint32_t bf[4];
                uint32_t off = (uint32_t)(((wn * 32 + nf * 8 + (lid & 7)) * RST +
                                           kh * 32 + (lid >> 3) * 8) * 2);
                ldsm4(bf, uB + off);
#pragma unroll
                for (int mf = 0; mf < 2; mf++)
#pragma unroll
                    for (int kk = 0; kk < 2; kk++)
                        mma_f16(acc[mf][nf], af[mf][kk], bf + kk * 2);
            }
        }
    }
    epi(acc);
}

// =====================================================================
// Kernel 1: QKV projection (z selects W). Epilogue -> Q/K fp16, V^T fp16.
// =====================================================================
__global__ __launch_bounds__(256, 2) void k_qkv() {
    const int tid = threadIdx.x, lid = tid & 31, w = tid >> 5;
    const int wm = w >> 1, wn = w & 1;
    const int m0 = blockIdx.x * 128, n0 = blockIdx.y * 64, z = blockIdx.z;
    const int g = lid >> 2, t = lid & 3;

    proj_gemm(g_xh, g_wh + (size_t)z * 262144, m0, n0, [&](float acc[2][4][4]) {
#pragma unroll
        for (int mf = 0; mf < 2; mf++) {
            int m = m0 + wm * 32 + mf * 16 + g;
            int b = m >> 11, s = m & 2047;
#pragma unroll
            for (int nf = 0; nf < 4; nf++) {
                int n = n0 + wn * 32 + nf * 8 + 2 * t;
                int h = n >> 6, d = n & 63;
                float* cc = acc[mf][nf];
                if (z < 2) {
                    __half* dst = (z == 0) ? g_qh : g_kh;
                    size_t o0 = ((size_t)(b * 8 + h) * 2048 + s) * 64 + d;
                    *(uint32_t*)(dst + o0) = packh2(cc[0], cc[1]);
                    *(uint32_t*)(dst + o0 + 512) = packh2(cc[2], cc[3]);  // row s+8
                } else {
                    size_t o0 = ((size_t)(b * 8 + h) * 64 + d) * 2048 + s;
                    g_vh[o0] = __float2half_rn(cc[0]);
                    g_vh[o0 + 2048] = __float2half_rn(cc[1]);
                    g_vh[o0 + 8] = __float2half_rn(cc[2]);
                    g_vh[o0 + 2056] = __float2half_rn(cc[3]);
                }
            }
        }
    });
}

// =====================================================================
// Kernel 3: output projection. Single-combo AO_fp16 @ Wo_fp16 -> fp32.
// =====================================================================
__global__ __launch_bounds__(256, 2) void k_out(float* __restrict__ out) {
    const int tid = threadIdx.x, lid = tid & 31, w = tid >> 5;
    const int wm = w >> 1, wn = w & 1;
    const int m0 = blockIdx.x * 128, n0 = blockIdx.y * 64;
    const int g = lid >> 2, t = lid & 3;

    proj_gemm(g_oh, g_wh + 3u * 262144, m0, n0, [&](float acc[2][4][4]) {
#pragma unroll
        for (int mf = 0; mf < 2; mf++) {
            int m = m0 + wm * 32 + mf * 16 + g;
#pragma unroll
            for (int nf = 0; nf < 4; nf++) {
                int n = n0 + wn * 32 + nf * 8 + 2 * t;
                float* cc = acc[mf][nf];
                *(float2*)(out + (size_t)m * 512 + n) = make_float2(cc[0], cc[1]);
                *(float2*)(out + (size_t)(m + 8) * 512 + n) = make_float2(cc[2], cc[3]);
            }
        }
    });
}

// =====================================================================
// Kernel 2: fused sigmoid attention. 256 thr, q-tile 256 (8 warps x 2
// m-halves x 16 rows), 2 CTAs/SM, 2-stage cp.async ring over kv tiles.
// Q staged once in smem (saves 64 persistent regs).
// stage layout (elems): K [0,9216) V [9216,17920); Q region after ring.
// =====================================================================
constexpr int KST = 72;                    // K-tile smem stride (elems)
constexpr int VST = 136;                   // V-tile smem stride (elems)
constexpr int TST = 17920;                 // stage elems
constexpr int QOFF = 2 * TST * 2;          // 71680 B: Q region byte offset
constexpr int ATTN_SMEM = QOFF + 256 * KST * 2;  // 71680 + 36864 = 108544 B

__global__ __launch_bounds__(256, 2) void k_attn() {
    extern __shared__ __half dsm[];
    const uint32_t u0 = smem_u32(dsm);
    const int tid = threadIdx.x, lid = tid & 31, w = tid >> 5;
    const int q0 = blockIdx.x * 256, bh = blockIdx.y;
    const int g = lid >> 2, t = lid & 3;
    const size_t qkBase = (size_t)bh * 2048 * 64;
    const size_t vBase = (size_t)bh * 131072;
    const uint32_t uQ = u0 + (uint32_t)QOFF;

    auto load_stage = [&](int j, int s) {
        uint32_t base = u0 + (uint32_t)(s * TST * 2);
        {   // K: 128 rows x 64 cols
            const int r0 = tid >> 3, q = tid & 7;
#pragma unroll
            for (int it = 0; it < 4; it++) {
                int r = r0 + it * 32;
                size_t src = qkBase + (size_t)(j * 128 + r) * 64 + q * 8;
                cp16(base + (uint32_t)((r * KST + q * 8) * 2), g_kh + src);
            }
        }
        {   // V: 64 rows x 128 cols
            const int r0 = tid >> 4, q = tid & 15;
#pragma unroll
            for (int it = 0; it < 4; it++) {
                int r = r0 + it * 16;
                size_t src = vBase + (size_t)j * 128 + (size_t)r * 2048 + q * 8;
                cp16(base + 18432 + (uint32_t)((r * VST + q * 8) * 2), g_vh + src);
            }
        }
    };

    // one-time Q stage (256 rows x 64 cols) + kv stage 0
    {
        const int r0 = tid >> 3, q = tid & 7;
#pragma unroll
        for (int it = 0; it < 8; it++) {
            int r = r0 + it * 32;
            size_t src = qkBase + (size_t)(q0 + r) * 64 + q * 8;
            cp16(uQ + (uint32_t)((r * KST + q * 8) * 2), g_qh + src);
        }
    }
    load_stage(0, 0);
    cp_commit();

    float oacc[2][8][4];
#pragma unroll
    for (int mh = 0; mh < 2; mh++)
#pragma unroll
        for (int nf = 0; nf < 8; nf++)
#pragma unroll
            for (int e = 0; e < 4; e++) oacc[mh][nf][e] = 0.0f;

    for (int j = 0; j < 16; j++) {
        cp_wait<0>();
        __syncthreads();
        if (j < 15) { load_stage(j + 1, (j + 1) & 1); cp_commit(); }

        const uint32_t base = u0 + (uint32_t)((j & 1) * TST * 2);
        const uint32_t uK = base, uV = base + 18432;

#pragma unroll
        for (int mh = 0; mh < 2; mh++) {
            // Q fragments for this m-half (from staged smem)
            uint32_t qf[4][4];
#pragma unroll
            for (int kk = 0; kk < 4; kk++) {
                uint32_t off = (uint32_t)(((mh * 128 + w * 16 + (lid & 15)) * KST +
                                           kk * 16 + (lid >> 4) * 8) * 2);
                ldsm4(qf[kk], uQ + off);
            }

            // process S in 4 chunks of 32 columns; PV for that chunk immediately
#pragma unroll
            for (int ck = 0; ck < 4; ck++) {
                float sacc[4][4];
#pragma unroll
                for (int nfl = 0; nfl < 4; nfl++)
#pragma unroll
                    for (int e = 0; e < 4; e++) sacc[nfl][e] = 0.0f;

#pragma unroll
                for (int nfl = 0; nfl < 4; nfl++) {
                    const int nf = ck * 4 + nfl;
                    uint32_t kf[8];
                    uint32_t b0 = (uint32_t)((nf * 8 + (lid & 7)) * KST + (lid >> 3) * 8);
                    ldsm4(kf, uK + b0 * 2);
                    ldsm4(kf + 4, uK + (b0 + 32) * 2);
#pragma unroll
                    for (int kk = 0; kk < 4; kk++) mma_f16(sacc[nfl], qf[kk], kf + 2 * kk);
                }

                // sigmoid (fp32 tanh path) + pack P fragments
                uint32_t ph[2][4];
#pragma unroll
                for (int u = 0; u < 2; u++) {
                    float* s0 = sacc[2 * u];
                    float* s1 = sacc[2 * u + 1];
                    ph[u][0] = packh2(sigmoid_tanh(s0[0]), sigmoid_tanh(s0[1]));
                    ph[u][1] = packh2(sigmoid_tanh(s0[2]), sigmoid_tanh(s0[3]));
                    ph[u][2] = packh2(sigmoid_tanh(s1[0]), sigmoid_tanh(s1[1]));
                    ph[u][3] = packh2(sigmoid_tanh(s1[2]), sigmoid_tanh(s1[3]));
                }

                // O += P @ V for this k-chunk
#pragma unroll
                for (int nf = 0; nf < 8; nf++) {
                    uint32_t vf[4];
                    uint32_t o0 =
                        (uint32_t)(((nf * 8 + (lid & 7)) * VST + ck * 32 + (lid >> 3) * 8) * 2);
                    ldsm4(vf, uV + o0);
                    mma_f16(oacc[mh][nf], ph[0], vf);
                    mma_f16(oacc[mh][nf], ph[1], vf + 2);
                }
            }
        }
    }

    // epilogue: O -> AO scratch fp16 [8192, 512], both m-halves
    {
        const int b = bh >> 3, h = bh & 7;
#pragma unroll
        for (int mh = 0; mh < 2; mh++) {
            const int s = q0 + mh * 128 + w * 16 + g;
#pragma unroll
            for (int nf = 0; nf < 8; nf++) {
                int d = nf * 8 + 2 * t;
                size_t o0 = ((size_t)b * 2048 + s) * 512 + h * 64 + d;
                *(uint32_t*)(g_oh + o0) = packh2(oacc[mh][nf][0], oacc[mh][nf][1]);
                *(uint32_t*)(g_oh + o0 + 8 * 512) = packh2(oacc[mh][nf][2], oacc[mh][nf][3]);
            }
        }
    }
}

// =====================================================================
extern "C" void kernel_launch(void* const* d_in, const int* in_sizes, int n_in,
                              void* d_out, int out_size) {
    const float* x = (const float*)d_in[0];
    const float* Wq = (const float*)d_in[1];
    const float* Wk = (const float*)d_in[2];
    const float* Wv = (const float*)d_in[3];
    const float* Wo = (const float*)d_in[4];
    float* out = (float*)d_out;

    cudaFuncSetAttribute(k_qkv, cudaFuncAttributeMaxDynamicSharedMemorySize, PROJ_SMEM);
    cudaFuncSetAttribute(k_out, cudaFuncAttributeMaxDynamicSharedMemorySize, PROJ_SMEM);
    cudaFuncSetAttribute(k_attn, cudaFuncAttributeMaxDynamicSharedMemorySize, ATTN_SMEM);

    k_split<<<5120, 256>>>(x, Wq, Wk, Wv, Wo);
    k_qkv<<<dim3(64, 8, 3), 256, PROJ_SMEM>>>();
    k_attn<<<dim3(8, 32), 256, ATTN_SMEM>>>();
    k_out<<<dim3(64, 8), 256, PROJ_SMEM>>>(out);
}

// round 17
// speedup vs baseline: 1.0855x; 1.0855x over previous
#include <cuda_runtime.h>
#include <cuda_bf16.h>
#include <cuda_fp16.h>
#include <stdint.h>

#define DI __device__ __forceinline__

// ---------------- scratch (static device globals; no allocation) ----------------
#define SCR_ELEMS (4u * 8u * 2048u * 64u)  // 4,194,304
__device__ __align__(16) __half g_qh[SCR_ELEMS];      // Q fp16: [B,H,S,D]
__device__ __align__(16) __half g_kh[SCR_ELEMS];      // K fp16: [B,H,S,D]
__device__ __align__(16) __half g_vh[SCR_ELEMS];      // V^T fp16: [B,H,D,S]
__device__ __align__(16) __half g_oh[SCR_ELEMS];      // AO fp16: [8192, 512]
__device__ __align__(16) __half g_xh[SCR_ELEMS];      // x fp16: [8192, 512]
__device__ __align__(16) __half g_wh[4u * 262144u];   // Wq,Wk,Wv,Wo fp16

// ---------------- helpers ----------------
DI uint32_t smem_u32(const void* p) {
    uint32_t a;
    asm("{ .reg .u64 t; cvta.to.shared.u64 t, %1; cvt.u32.u64 %0, t; }" : "=r"(a) : "l"(p));
    return a;
}
DI void ldsm4(uint32_t* r, uint32_t a) {
    asm volatile("ldmatrix.sync.aligned.m8n8.x4.shared.b16 {%0,%1,%2,%3}, [%4];"
                 : "=r"(r[0]), "=r"(r[1]), "=r"(r[2]), "=r"(r[3]) : "r"(a));
}
DI void mma_f16(float* c, const uint32_t* a, const uint32_t* b) {
    asm volatile(
        "mma.sync.aligned.m16n8k16.row.col.f32.f16.f16.f32 "
        "{%0,%1,%2,%3}, {%4,%5,%6,%7}, {%8,%9}, {%0,%1,%2,%3};"
        : "+f"(c[0]), "+f"(c[1]), "+f"(c[2]), "+f"(c[3])
        : "r"(a[0]), "r"(a[1]), "r"(a[2]), "r"(a[3]), "r"(b[0]), "r"(b[1]));
}
DI void cp16(uint32_t dst, const void* src) {
    asm volatile("cp.async.cg.shared.global [%0], [%1], 16;" :: "r"(dst), "l"(src));
}
DI void cp_commit() { asm volatile("cp.async.commit_group;" ::: "memory"); }
template <int N> DI void cp_wait() { asm volatile("cp.async.wait_group %0;" :: "n"(N) : "memory"); }

DI uint32_t packh2(float a, float b) {
    __half2 h = __floats2half2_rn(a, b);
    return *reinterpret_cast<uint32_t*>(&h);
}
// sigmoid(qk/8 - log 2048) = 0.5 + 0.5*tanh((qk/8 - log2048)/2)  — fp32 MUFU
DI float sigmoid_tanh(float qk) {
    float t = fmaf(qk, 0.0625f, -3.81230949f);  // qk/16 - log(2048)/2
    float th;
    asm("tanh.approx.f32 %0, %1;" : "=f"(th) : "f"(t));
    return fmaf(th, 0.5f, 0.5f);
}

// =====================================================================
// Kernel 0: pre-convert x and weights to fp16.
// =====================================================================
__global__ __launch_bounds__(256) void k_split(const float* __restrict__ x,
                                               const float* __restrict__ Wq,
                                               const float* __restrict__ Wk,
                                               const float* __restrict__ Wv,
                                               const float* __restrict__ Wo) {
    size_t idx = (size_t)blockIdx.x * 256 + threadIdx.x;
    if (idx < 1048576) {
        float4 f = ((const float4*)x)[idx];
        ((uint2*)g_xh)[idx] = make_uint2(packh2(f.x, f.y), packh2(f.z, f.w));
    } else {
        size_t r = idx - 1048576;
        int ws = (int)(r >> 16);
        size_t off = r & 65535;
        const float* src = (ws == 0) ? Wq : (ws == 1) ? Wk : (ws == 2) ? Wv : Wo;
        float4 f = ((const float4*)src)[off];
        ((uint2*)(g_wh + (size_t)ws * 262144))[off] =
            make_uint2(packh2(f.x, f.y), packh2(f.z, f.w));
    }
}

// =====================================================================
// Shared proj-GEMM: BM=128 BN=64 BK=64, 256 thr (8 warps 4m x 2n),
// 3-stage cp.async ring (wait<1>), single-combo A_fp16 @ B_fp16.
// stage elems: 13824.  layout: A [0,9216) B [9216,13824)
// =====================================================================
constexpr int RST = 72;   // padded row stride (elems) for 64-col tiles
constexpr int PST = 13824;
constexpr int PROJ_SMEM = 3 * PST * 2;  // 82944 B

template <typename EPI>
DI void proj_gemm(const __half* __restrict__ A, const __half* __restrict__ B,
                  int m0, int n0, EPI epi) {
    extern __shared__ __half dsm[];
    const uint32_t u0 = smem_u32(dsm);
    const int tid = threadIdx.x, lid = tid & 31, w = tid >> 5;
    const int wm = w >> 1, wn = w & 1;

    auto load_stage = [&](int c, int s) {
        uint32_t base = u0 + (uint32_t)(s * PST * 2);
        const int r0 = tid >> 3, q = tid & 7;
#pragma unroll
        for (int it = 0; it < 4; it++) {
            int r = r0 + it * 32;
            size_t src = (size_t)(m0 + r) * 512 + c * 64 + q * 8;
            cp16(base + (uint32_t)((r * RST + q * 8) * 2), A + src);
        }
#pragma unroll
        for (int it = 0; it < 2; it++) {
            int r = r0 + it * 32;
            size_t src = (size_t)(n0 + r) * 512 + c * 64 + q * 8;
            cp16(base + 18432u + (uint32_t)((r * RST + q * 8) * 2), B + src);
        }
    };

    float acc[2][4][4];
#pragma unroll
    for (int mf = 0; mf < 2; mf++)
#pragma unroll
        for (int nf = 0; nf < 4; nf++)
#pragma unroll
            for (int e = 0; e < 4; e++) acc[mf][nf][e] = 0.0f;

    load_stage(0, 0); cp_commit();
    load_stage(1, 1); cp_commit();

    for (int c = 0; c < 8; c++) {
        if (c < 7) cp_wait<1>(); else cp_wait<0>();
        __syncthreads();
        if (c < 6) { load_stage(c + 2, (c + 2) % 3); cp_commit(); }

        const uint32_t bA = u0 + (uint32_t)((c % 3) * PST * 2);
        const uint32_t uA = bA, uB = bA + 18432u;

#pragma unroll
        for (int kh = 0; kh < 2; kh++) {
            uint32_t af[2][2][4];
#pragma unroll
            for (int mf = 0; mf < 2; mf++)
#pragma unroll
                for (int kk = 0; kk < 2; kk++) {
                    uint32_t off = (uint32_t)(((wm * 32 + mf * 16 + (lid & 15)) * RST +
                                               kh * 32 + kk * 16 + (lid >> 4) * 8) * 2);
                    ldsm4(af[mf][kk], uA + off);
                }
#pragma unroll
            for (int nf = 0; nf < 4; nf++) {
                uint32_t bf[4];
                uint32_t off = (uint32_t)(((wn * 32 + nf * 8 + (lid & 7)) * RST +
                                           kh * 32 + (lid >> 3) * 8) * 2);
                ldsm4(bf, uB + off);
#pragma unroll
                for (int mf = 0; mf < 2; mf++)
#pragma unroll
                    for (int kk = 0; kk < 2; kk++)
                        mma_f16(acc[mf][nf], af[mf][kk], bf + kk * 2);
            }
        }
    }
    epi(acc);
}

// =====================================================================
// Kernel 1: QKV projection (z selects W). Epilogue -> Q/K fp16, V^T fp16.
// =====================================================================
__global__ __launch_bounds__(256, 2) void k_qkv() {
    const int tid = threadIdx.x, lid = tid & 31, w = tid >> 5;
    const int wm = w >> 1, wn = w & 1;
    const int m0 = blockIdx.x * 128, n0 = blockIdx.y * 64, z = blockIdx.z;
    const int g = lid >> 2, t = lid & 3;

    proj_gemm(g_xh, g_wh + (size_t)z * 262144, m0, n0, [&](float acc[2][4][4]) {
#pragma unroll
        for (int mf = 0; mf < 2; mf++) {
            int m = m0 + wm * 32 + mf * 16 + g;
            int b = m >> 11, s = m & 2047;
#pragma unroll
            for (int nf = 0; nf < 4; nf++) {
                int n = n0 + wn * 32 + nf * 8 + 2 * t;
                int h = n >> 6, d = n & 63;
                float* cc = acc[mf][nf];
                if (z < 2) {
                    __half* dst = (z == 0) ? g_qh : g_kh;
                    size_t o0 = ((size_t)(b * 8 + h) * 2048 + s) * 64 + d;
                    *(uint32_t*)(dst + o0) = packh2(cc[0], cc[1]);
                    *(uint32_t*)(dst + o0 + 512) = packh2(cc[2], cc[3]);  // row s+8
                } else {
                    size_t o0 = ((size_t)(b * 8 + h) * 64 + d) * 2048 + s;
                    g_vh[o0] = __float2half_rn(cc[0]);
                    g_vh[o0 + 2048] = __float2half_rn(cc[1]);
                    g_vh[o0 + 8] = __float2half_rn(cc[2]);
                    g_vh[o0 + 2056] = __float2half_rn(cc[3]);
                }
            }
        }
    });
}

// =====================================================================
// Kernel 3: output projection. Single-combo AO_fp16 @ Wo_fp16 -> fp32.
// =====================================================================
__global__ __launch_bounds__(256, 2) void k_out(float* __restrict__ out) {
    const int tid = threadIdx.x, lid = tid & 31, w = tid >> 5;
    const int wm = w >> 1, wn = w & 1;
    const int m0 = blockIdx.x * 128, n0 = blockIdx.y * 64;
    const int g = lid >> 2, t = lid & 3;

    proj_gemm(g_oh, g_wh + 3u * 262144, m0, n0, [&](float acc[2][4][4]) {
#pragma unroll
        for (int mf = 0; mf < 2; mf++) {
            int m = m0 + wm * 32 + mf * 16 + g;
#pragma unroll
            for (int nf = 0; nf < 4; nf++) {
                int n = n0 + wn * 32 + nf * 8 + 2 * t;
                float* cc = acc[mf][nf];
                *(float2*)(out + (size_t)m * 512 + n) = make_float2(cc[0], cc[1]);
                *(float2*)(out + (size_t)(m + 8) * 512 + n) = make_float2(cc[2], cc[3]);
            }
        }
    });
}

// =====================================================================
// Kernel 2: fused sigmoid attention. 256 thr, q-tile 256: 8 warps x
// 32 rows (2 m-frags). K/V fragments loaded ONCE per warp and reused
// across both m-frags (halves ldsm crossbar traffic per unit work).
// 1 CTA/SM (natural regs ~170), 3-stage cp.async ring over kv tiles.
// stage layout (elems): K [0,9216) V [9216,17920)
// =====================================================================
constexpr int KST = 72;                    // K-tile smem stride (elems)
constexpr int VST = 136;                   // V-tile smem stride (elems)
constexpr int TST = 17920;                 // stage elems
constexpr int ATTN_SMEM = 3 * TST * 2;     // 107520 B

__global__ __launch_bounds__(256, 1) void k_attn() {
    extern __shared__ __half dsm[];
    const uint32_t u0 = smem_u32(dsm);
    const int tid = threadIdx.x, lid = tid & 31, w = tid >> 5;
    const int q0 = blockIdx.x * 256, bh = blockIdx.y;
    const int g = lid >> 2, t = lid & 3;
    const size_t qkBase = (size_t)bh * 2048 * 64;
    const size_t vBase = (size_t)bh * 131072;

    auto load_stage = [&](int j, int s) {
        uint32_t base = u0 + (uint32_t)(s * TST * 2);
        {   // K: 128 rows x 64 cols
            const int r0 = tid >> 3, q = tid & 7;
#pragma unroll
            for (int it = 0; it < 4; it++) {
                int r = r0 + it * 32;
                size_t src = qkBase + (size_t)(j * 128 + r) * 64 + q * 8;
                cp16(base + (uint32_t)((r * KST + q * 8) * 2), g_kh + src);
            }
        }
        {   // V: 64 rows x 128 cols
            const int r0 = tid >> 4, q = tid & 15;
#pragma unroll
            for (int it = 0; it < 4; it++) {
                int r = r0 + it * 16;
                size_t src = vBase + (size_t)j * 128 + (size_t)r * 2048 + q * 8;
                cp16(base + 18432 + (uint32_t)((r * VST + q * 8) * 2), g_vh + src);
            }
        }
    };

    load_stage(0, 0); cp_commit();
    load_stage(1, 1); cp_commit();

    // Q fragments for this warp's 32 rows (2 m-frags, resident whole kernel)
    uint32_t qf[2][4][4];
#pragma unroll
    for (int mh = 0; mh < 2; mh++) {
        const __half* Q = g_qh + qkBase + (size_t)(q0 + w * 32 + mh * 16) * 64;
#pragma unroll
        for (int kk = 0; kk < 4; kk++) {
            int c0 = kk * 16 + 2 * t;
            qf[mh][kk][0] = *(const uint32_t*)(Q + g * 64 + c0);
            qf[mh][kk][1] = *(const uint32_t*)(Q + (g + 8) * 64 + c0);
            qf[mh][kk][2] = *(const uint32_t*)(Q + g * 64 + c0 + 8);
            qf[mh][kk][3] = *(const uint32_t*)(Q + (g + 8) * 64 + c0 + 8);
        }
    }

    float oacc[2][8][4];
#pragma unroll
    for (int mh = 0; mh < 2; mh++)
#pragma unroll
        for (int nf = 0; nf < 8; nf++)
#pragma unroll
            for (int e = 0; e < 4; e++) oacc[mh][nf][e] = 0.0f;

    for (int j = 0; j < 16; j++) {
        if (j < 15) cp_wait<1>(); else cp_wait<0>();
        __syncthreads();
        if (j < 14) { load_stage(j + 2, (j + 2) % 3); cp_commit(); }

        const uint32_t base = u0 + (uint32_t)((j % 3) * TST * 2);
        const uint32_t uK = base, uV = base + 18432;

        // process S in 4 chunks of 32 columns; PV for that chunk immediately
#pragma unroll
        for (int ck = 0; ck < 4; ck++) {
            float sacc[2][4][4];
#pragma unroll
            for (int mh = 0; mh < 2; mh++)
#pragma unroll
                for (int nfl = 0; nfl < 4; nfl++)
#pragma unroll
                    for (int e = 0; e < 4; e++) sacc[mh][nfl][e] = 0.0f;

#pragma unroll
            for (int nfl = 0; nfl < 4; nfl++) {
                const int nf = ck * 4 + nfl;
                uint32_t kf[8];
                uint32_t b0 = (uint32_t)((nf * 8 + (lid & 7)) * KST + (lid >> 3) * 8);
                ldsm4(kf, uK + b0 * 2);
                ldsm4(kf + 4, uK + (b0 + 32) * 2);
                // reuse kf for both m-frags
#pragma unroll
                for (int kk = 0; kk < 4; kk++) {
                    mma_f16(sacc[0][nfl], qf[0][kk], kf + 2 * kk);
                    mma_f16(sacc[1][nfl], qf[1][kk], kf + 2 * kk);
                }
            }

            // sigmoid (fp32 tanh path) + pack P fragments, both m-frags
            uint32_t ph[2][2][4];
#pragma unroll
            for (int mh = 0; mh < 2; mh++)
#pragma unroll
                for (int u = 0; u < 2; u++) {
                    float* s0 = sacc[mh][2 * u];
                    float* s1 = sacc[mh][2 * u + 1];
                    ph[mh][u][0] = packh2(sigmoid_tanh(s0[0]), sigmoid_tanh(s0[1]));
                    ph[mh][u][1] = packh2(sigmoid_tanh(s0[2]), sigmoid_tanh(s0[3]));
                    ph[mh][u][2] = packh2(sigmoid_tanh(s1[0]), sigmoid_tanh(s1[1]));
                    ph[mh][u][3] = packh2(sigmoid_tanh(s1[2]), sigmoid_tanh(s1[3]));
                }

            // O += P @ V for this k-chunk; vf reused for both m-frags
#pragma unroll
            for (int nf = 0; nf < 8; nf++) {
                uint32_t vf[4];
                uint32_t o0 =
                    (uint32_t)(((nf * 8 + (lid & 7)) * VST + ck * 32 + (lid >> 3) * 8) * 2);
                ldsm4(vf, uV + o0);
                mma_f16(oacc[0][nf], ph[0][0], vf);
                mma_f16(oacc[0][nf], ph[0][1], vf + 2);
                mma_f16(oacc[1][nf], ph[1][0], vf);
                mma_f16(oacc[1][nf], ph[1][1], vf + 2);
            }
        }
    }

    // epilogue: O -> AO scratch fp16 [8192, 512], both m-frags
    {
        const int b = bh >> 3, h = bh & 7;
#pragma unroll
        for (int mh = 0; mh < 2; mh++) {
            const int s = q0 + w * 32 + mh * 16 + g;
#pragma unroll
            for (int nf = 0; nf < 8; nf++) {
                int d = nf * 8 + 2 * t;
                size_t o0 = ((size_t)b * 2048 + s) * 512 + h * 64 + d;
                *(uint32_t*)(g_oh + o0) = packh2(oacc[mh][nf][0], oacc[mh][nf][1]);
                *(uint32_t*)(g_oh + o0 + 8 * 512) = packh2(oacc[mh][nf][2], oacc[mh][nf][3]);
            }
        }
    }
}

// =====================================================================
extern "C" void kernel_launch(void* const* d_in, const int* in_sizes, int n_in,
                              void* d_out, int out_size) {
    const float* x = (const float*)d_in[0];
    const float* Wq = (const float*)d_in[1];
    const float* Wk = (const float*)d_in[2];
    const float* Wv = (const float*)d_in[3];
    const float* Wo = (const float*)d_in[4];
    float* out = (float*)d_out;

    cudaFuncSetAttribute(k_qkv, cudaFuncAttributeMaxDynamicSharedMemorySize, PROJ_SMEM);
    cudaFuncSetAttribute(k_out, cudaFuncAttributeMaxDynamicSharedMemorySize, PROJ_SMEM);
    cudaFuncSetAttribute(k_attn, cudaFuncAttributeMaxDynamicSharedMemorySize, ATTN_SMEM);

    k_split<<<5120, 256>>>(x, Wq, Wk, Wv, Wo);
    k_qkv<<<dim3(64, 8, 3), 256, PROJ_SMEM>>>();
    k_attn<<<dim3(8, 32), 256, ATTN_SMEM>>>();
    k_out<<<dim3(64, 8), 256, PROJ_SMEM>>>(out);
}